// round 14
// baseline (speedup 1.0000x reference)
#include <cuda_runtime.h>
#include <cuda_bf16.h>

// TargetedDropout inference path:
//   per channel c (last axis, C=1024), threshold = 16383-th smallest |x| over
//   the N=32768 leading entries; out = (|x| <= thr[c]) ? 0 : x.
//
// Round 13: collect MLP 4->8 (launch_bounds-capped regs); select dispatch is
// register-staged (regions loaded as 6 independent uint4 before the serial
// cur[u]++ chain); mask gets streaming cache hints. Algorithm unchanged:
// exact packed-histogram select + exact radix fallback per column.

#define C_DIM   1024
#define N_ROWS  32768
#define RANK0   16383            // int(0.5 * 32768) - 1
#define W_LO    0.64f
#define W_HI    0.71f
#define NBLK    1024             // collect blocks
#define RPB     (N_ROWS / NBLK)  // 32 rows per collect block
#define NGRP    256              // column groups (4 cols each)
#define CAPT    24               // per (group,blk) region cap (lambda = 5.69)
#define CAPC    1664             // per-column shared capacity (mean 1457, +5.5 sd)
#define SMALLC  96               // bin-mate capacity (Poisson(~5) at 2048 bins)
#define MSK23   0x007FFFFFu

// [group][blk][CAPT] tagged candidates: mantissa | (col_in_group << 23).
// Region = 96 B, 16B-aligned (24 words).
__device__ unsigned g_cand[(size_t)NGRP * NBLK * CAPT];
// [group][blk] packed meta: .x = 4x8b per-col candidate counts,
//                           .y = 4x8b per-col below counts.  2 MB.
__device__ uint2    g_meta[NGRP * NBLK];
__device__ __align__(16) float g_thr[C_DIM];

// -------------------------------------------------------------------------
// Pass 1: one full read of x. Thread t exclusively owns columns 4t..4t+3
// within its block; its candidates append to ONE contiguous region.
// grid = 1024 blocks x 256 threads; each block covers 32 rows. MLP = 8.
// -------------------------------------------------------------------------
__global__ void __launch_bounds__(256, 5) k_collect(const float4* __restrict__ x) {
    const int t    = threadIdx.x;            // == column group id
    const int blk  = blockIdx.x;
    const int row0 = blk * RPB;

    unsigned* cp = &g_cand[((size_t)t * NBLK + blk) * CAPT];

    int n_all = 0;        // total candidates appended to region
    unsigned cnts = 0;    // 4x8b per-col candidate counts
    unsigned bels = 0;    // 4x8b per-col below counts

#define PROC1(a, u)                                                           \
    do {                                                                      \
        bels += (unsigned)((a) < W_LO) << (8 * (u));                          \
        if ((a) >= W_LO && (a) <= W_HI) {                                     \
            if (n_all < CAPT)                                                 \
                cp[n_all] = (__float_as_uint(a) & MSK23) | ((unsigned)(u) << 23); \
            n_all++;                                                          \
            cnts += 1u << (8 * (u));                                          \
        }                                                                     \
    } while (0)

#define PROC(v)                                                               \
    do {                                                                      \
        PROC1(fabsf((v).x), 0);                                               \
        PROC1(fabsf((v).y), 1);                                               \
        PROC1(fabsf((v).z), 2);                                               \
        PROC1(fabsf((v).w), 3);                                               \
    } while (0)

    #pragma unroll
    for (int j0 = 0; j0 < RPB; j0 += 8) {
        // Front-batched independent loads: MLP = 8.
        float4 v0 = x[(size_t)(row0 + j0 + 0) * 256 + t];
        float4 v1 = x[(size_t)(row0 + j0 + 1) * 256 + t];
        float4 v2 = x[(size_t)(row0 + j0 + 2) * 256 + t];
        float4 v3 = x[(size_t)(row0 + j0 + 3) * 256 + t];
        float4 v4 = x[(size_t)(row0 + j0 + 4) * 256 + t];
        float4 v5 = x[(size_t)(row0 + j0 + 5) * 256 + t];
        float4 v6 = x[(size_t)(row0 + j0 + 6) * 256 + t];
        float4 v7 = x[(size_t)(row0 + j0 + 7) * 256 + t];
        PROC(v0); PROC(v1); PROC(v2); PROC(v3);
        PROC(v4); PROC(v5); PROC(v6); PROC(v7);
    }
#undef PROC
#undef PROC1

    g_meta[t * NBLK + blk] = make_uint2(cnts, bels);
}

// -------------------------------------------------------------------------
// Pass 2: one block per GROUP g (columns 4g..4g+3). Coalesced meta reads,
// packed 16-bit shfl scans for per-column dispatch offsets, register-staged
// region loads feeding the dispatch chain, then ALL FOUR selections
// concurrently via packed dual 2048-bin histograms (bins = mantissa bits
// [22:12]; values share exponent 126 so mantissa order == value order).
// Fallback (rank outside window / any overflow): exact radix select.
// -------------------------------------------------------------------------
__global__ void __launch_bounds__(256) k_select(const float* __restrict__ x) {
    __shared__ unsigned sdata[4][CAPC];   // 26.6 KB
    __shared__ int      histA[2048];      // col0 lo16 | col2 hi16
    __shared__ int      histB[2048];      // col1 lo16 | col3 hi16
    __shared__ unsigned ssmall[4][SMALLC];
    __shared__ int      s_smc[4];
    __shared__ int      s_bel[4], s_n[4], s_r[4], s_fb[4];
    __shared__ int      s_bin[4], s_r2[4];
    __shared__ int      s_any_over;
    __shared__ int      wsumA[8], wsumB[8];
    __shared__ unsigned s_prefix;
    __shared__ int      s_rank;

    const int g    = blockIdx.x;
    const int t    = threadIdx.x;
    const int lane = t & 31;
    const int wid  = t >> 5;

    if (t < 4) { s_bel[t] = 0; s_fb[t] = 0; s_smc[t] = 0; }
    if (t == 0) s_any_over = 0;
    __syncthreads();

    // ---- meta for my 4 regions (coalesced 32B/thread) ----
    int mtot[4];          // clamped region totals (safe read bound)
    int tc0 = 0, tc1 = 0, tc2 = 0, tc3 = 0;
    int bel0 = 0, bel1 = 0, bel2 = 0, bel3 = 0;
    bool over = false;
    #pragma unroll
    for (int rr = 0; rr < 4; ++rr) {
        const uint2 m = g_meta[g * NBLK + (t * 4 + rr)];
        const int b0 = (int)(m.x & 255u),         b1 = (int)((m.x >> 8) & 255u);
        const int b2 = (int)((m.x >> 16) & 255u), b3 = (int)(m.x >> 24);
        const int gt = b0 + b1 + b2 + b3;
        if (gt > CAPT) over = true;
        mtot[rr] = (gt > CAPT) ? CAPT : gt;
        tc0 += b0;  tc1 += b1;  tc2 += b2;  tc3 += b3;
        bel0 += (int)(m.y & 255u);         bel1 += (int)((m.y >> 8) & 255u);
        bel2 += (int)((m.y >> 16) & 255u); bel3 += (int)(m.y >> 24);
    }
    if (over) s_any_over = 1;
    atomicAdd(&s_bel[0], bel0);  atomicAdd(&s_bel[1], bel1);
    atomicAdd(&s_bel[2], bel2);  atomicAdd(&s_bel[3], bel3);

    // ---- packed 16-bit exclusive scans for dispatch offsets ----
    const int A = tc0 | (tc2 << 16);
    const int B = tc1 | (tc3 << 16);
    int iA = A, iB = B;
    #pragma unroll
    for (int d = 1; d < 32; d <<= 1) {
        int oA = __shfl_up_sync(0xFFFFFFFFu, iA, d);
        int oB = __shfl_up_sync(0xFFFFFFFFu, iB, d);
        if (lane >= d) { iA += oA; iB += oB; }
    }
    if (lane == 31) { wsumA[wid] = iA; wsumB[wid] = iB; }
    __syncthreads();
    if (t == 0) {
        int aA = 0, aB = 0;
        #pragma unroll
        for (int i = 0; i < 8; ++i) {
            int ta = wsumA[i], tb = wsumB[i];
            wsumA[i] = aA; wsumB[i] = aB;
            aA += ta; aB += tb;
        }
        s_n[0] = aA & 0xFFFF;  s_n[2] = aA >> 16;
        s_n[1] = aB & 0xFFFF;  s_n[3] = aB >> 16;
    }
    __syncthreads();

    if (t < 4) {
        const int n = s_n[t];
        const int r = RANK0 - s_bel[t];
        s_r[t] = r;
        s_fb[t] = (s_any_over || n > CAPC || r < 0 || r >= n) ? 1 : 0;
    }

    const int eA = wsumA[wid] + iA - A;
    const int eB = wsumB[wid] + iB - B;
    int cur[4];
    cur[0] = eA & 0xFFFF;  cur[2] = eA >> 16;
    cur[1] = eB & 0xFFFF;  cur[3] = eB >> 16;

    // ---- dispatch: stage each region in registers (6 independent uint4
    //      loads, MLP=6), then a fully-unrolled predicated dispatch chain ----
    #pragma unroll
    for (int rr = 0; rr < 4; ++rr) {
        const uint4* src = reinterpret_cast<const uint4*>(
            &g_cand[((size_t)g * NBLK + (t * 4 + rr)) * CAPT]);
        const uint4 q0 = src[0], q1 = src[1], q2 = src[2];
        const uint4 q3 = src[3], q4 = src[4], q5 = src[5];
        const unsigned wbuf[CAPT] = {
            q0.x, q0.y, q0.z, q0.w, q1.x, q1.y, q1.z, q1.w,
            q2.x, q2.y, q2.z, q2.w, q3.x, q3.y, q3.z, q3.w,
            q4.x, q4.y, q4.z, q4.w, q5.x, q5.y, q5.z, q5.w };
        const int m = mtot[rr];
        #pragma unroll
        for (int j = 0; j < CAPT; ++j) {
            if (j < m) {
                const unsigned w = wbuf[j];
                const int u = (int)(w >> 23);
                const int o = cur[u]++;
                if (o < CAPC) sdata[u][o] = w & MSK23;
            }
        }
    }

    // ---- zero packed histograms ----
    #pragma unroll
    for (int q = 0; q < 8; ++q) { histA[t + q * 256] = 0; histB[t + q * 256] = 0; }
    __syncthreads();

    // ---- one histogram pass covering all four columns (packed adds) ----
    {
        const int nu0 = s_fb[0] ? 0 : s_n[0];
        const int nu1 = s_fb[1] ? 0 : s_n[1];
        const int nu2 = s_fb[2] ? 0 : s_n[2];
        const int nu3 = s_fb[3] ? 0 : s_n[3];
        for (int i = t; i < nu0; i += 256) atomicAdd(&histA[sdata[0][i] >> 12], 1);
        for (int i = t; i < nu1; i += 256) atomicAdd(&histB[sdata[1][i] >> 12], 1);
        for (int i = t; i < nu2; i += 256) atomicAdd(&histA[sdata[2][i] >> 12], 1 << 16);
        for (int i = t; i < nu3; i += 256) atomicAdd(&histB[sdata[3][i] >> 12], 1 << 16);
    }
    __syncthreads();

    // ---- packed segment sums (8 bins each) + packed scans ----
    int sA = 0, sB = 0;
    #pragma unroll
    for (int q = 0; q < 8; ++q) { sA += histA[t * 8 + q]; sB += histB[t * 8 + q]; }
    int jA = sA, jB = sB;
    #pragma unroll
    for (int d = 1; d < 32; d <<= 1) {
        int oA = __shfl_up_sync(0xFFFFFFFFu, jA, d);
        int oB = __shfl_up_sync(0xFFFFFFFFu, jB, d);
        if (lane >= d) { jA += oA; jB += oB; }
    }
    if (lane == 31) { wsumA[wid] = jA; wsumB[wid] = jB; }
    __syncthreads();
    if (t == 0) {
        int aA = 0, aB = 0;
        #pragma unroll
        for (int i = 0; i < 8; ++i) {
            int ta = wsumA[i], tb = wsumB[i];
            wsumA[i] = aA; wsumB[i] = aB;
            aA += ta; aB += tb;
        }
    }
    __syncthreads();
    const int exA = wsumA[wid] + jA - sA;   // packed exclusive prefixes
    const int exB = wsumB[wid] + jB - sB;

    // ---- parallel rank-segment location: the one thread whose segment
    //      contains r walks its <=8 bins. Four columns concurrently. ----
#define FIND(uu, HH, ex, sg, SH)                                              \
    do {                                                                      \
        if (!s_fb[uu]) {                                                      \
            const int r_ = s_r[uu];                                           \
            const int e_ = ((ex) >> (SH)) & 0xFFFF;                           \
            const int g_ = ((sg) >> (SH)) & 0xFFFF;                           \
            if (e_ <= r_ && r_ < e_ + g_) {                                   \
                int cum = e_, b = t * 8;                                      \
                while (cum + (int)(((unsigned)HH[b] >> (SH)) & 0xFFFFu) <= r_) { \
                    cum += (int)(((unsigned)HH[b] >> (SH)) & 0xFFFFu);        \
                    ++b;                                                      \
                }                                                             \
                s_bin[uu] = b;                                                \
                s_r2[uu]  = r_ - cum;                                         \
            }                                                                 \
        }                                                                     \
    } while (0)
    FIND(0, histA, exA, sA, 0);
    FIND(1, histB, exB, sB, 0);
    FIND(2, histA, exA, sA, 16);
    FIND(3, histB, exB, sB, 16);
#undef FIND
    __syncthreads();

    // ---- bin-mate collection: one pass over each column's shared array ----
    #pragma unroll
    for (int u = 0; u < 4; ++u) {
        if (!s_fb[u]) {
            const int n = s_n[u];
            const unsigned bsel = (unsigned)s_bin[u];
            const unsigned* sd = sdata[u];
            for (int i = t; i < n; i += 256) {
                if ((sd[i] >> 12) == bsel) {
                    int p = atomicAdd(&s_smc[u], 1);
                    if (p < SMALLC) ssmall[u][p] = sd[i];
                }
            }
        }
    }
    __syncthreads();

    // ---- resolve: threads 0..3 handle one column each (m ~ 5) ----
    if (t < 4 && !s_fb[t]) {
        const int m = s_smc[t];
        if (m > SMALLC) {
            s_fb[t] = 1;                       // pathological: redo exactly
        } else {
            const int r2 = s_r2[t];
            unsigned ans = 0;
            for (int i = 0; i < m; ++i) {
                unsigned vv = ssmall[t][i];
                int less = 0, eq = 0;
                for (int j = 0; j < m; ++j) {
                    less += (ssmall[t][j] < vv);
                    eq   += (ssmall[t][j] == vv);
                }
                if (less <= r2 && r2 < less + eq) { ans = vv; break; }
            }
            g_thr[g * 4 + t] = __uint_as_float(ans | (126u << 23));
        }
    }
    __syncthreads();

    // ---- exact MSD radix-select fallback for any flagged column ----
    for (int u = 0; u < 4; ++u) {
        if (s_fb[u]) {
            const int c = g * 4 + u;
            if (t == 0) { s_prefix = 0; s_rank = RANK0; }
            for (int shift = 24; shift >= 0; shift -= 8) {
                histA[t] = 0;                  // only 256 bins used here
                __syncthreads();
                const unsigned pfx = s_prefix;
                const int hs = shift + 8;
                for (int row = t; row < N_ROWS; row += 256) {
                    unsigned key = __float_as_uint(fabsf(x[(size_t)row * C_DIM + c]));
                    bool ok = (hs >= 32) || ((key >> hs) == (pfx >> hs));
                    if (ok) atomicAdd(&histA[(key >> shift) & 255], 1);
                }
                __syncthreads();
                if (t == 0) {
                    int cum = 0, b = 0;
                    while (cum + histA[b] <= s_rank) { cum += histA[b]; ++b; }
                    s_rank  -= cum;
                    s_prefix |= ((unsigned)b) << shift;
                }
                __syncthreads();
            }
            if (t == 0) g_thr[c] = __uint_as_float(s_prefix);
            __syncthreads();
        }
    }
}

// -------------------------------------------------------------------------
// Pass 3: streaming mask with streaming cache hints (x and out are not
// re-read). blockDim must be 256 so each thread's column group (threadIdx.x)
// is loop-invariant -> threshold float4 hoisted out of the loop.
// -------------------------------------------------------------------------
__global__ void __launch_bounds__(256) k_mask(const float4* __restrict__ x,
                                              float4* __restrict__ out,
                                              int n4) {
    const float4 thr = reinterpret_cast<const float4*>(g_thr)[threadIdx.x];
    const int stride = gridDim.x * blockDim.x;   // multiple of 256
    for (int i = blockIdx.x * blockDim.x + threadIdx.x; i < n4; i += stride) {
        float4 v = __ldcs(&x[i]);
        float4 o;
        o.x = (fabsf(v.x) <= thr.x) ? 0.0f : v.x;
        o.y = (fabsf(v.y) <= thr.y) ? 0.0f : v.y;
        o.z = (fabsf(v.z) <= thr.z) ? 0.0f : v.z;
        o.w = (fabsf(v.w) <= thr.w) ? 0.0f : v.w;
        __stcs(&out[i], o);
    }
}

extern "C" void kernel_launch(void* const* d_in, const int* in_sizes, int n_in,
                              void* d_out, int out_size) {
    const float* x = (const float*)d_in[0];
    float* out     = (float*)d_out;
    const int n4   = out_size / 4;               // 8,388,608 float4s

    k_collect<<<NBLK, 256>>>((const float4*)x);
    k_select <<<NGRP, 256>>>(x);
    k_mask   <<<8192, 256>>>((const float4*)x, (float4*)out, n4);
}

// round 15
// speedup vs baseline: 1.0889x; 1.0889x over previous
#include <cuda_runtime.h>
#include <cuda_bf16.h>

// TargetedDropout inference path:
//   per channel c (last axis, C=1024), threshold = 16383-th smallest |x| over
//   the N=32768 leading entries; out = (|x| <= thr[c]) ? 0 : x.
//
// Round 14: collect and mask reverted to the proven R13 config. Select loses
// its dispatch/sdata stage entirely: packed dual 2048-bin histograms are
// built DIRECTLY from the global region stream (tag -> histogram half), and
// bin-mates are gathered on a second, cache-resident region sweep.
// Exact select; exact radix fallback per column.

#define C_DIM   1024
#define N_ROWS  32768
#define RANK0   16383            // int(0.5 * 32768) - 1
#define W_LO    0.64f
#define W_HI    0.71f
#define NBLK    1024             // collect blocks
#define RPB     (N_ROWS / NBLK)  // 32 rows per collect block
#define NGRP    256              // column groups (4 cols each)
#define CAPT    24               // per (group,blk) region cap (lambda = 5.69)
#define SMALLC  96               // bin-mate capacity (Poisson(~5) at 2048 bins)
#define MSK23   0x007FFFFFu

// [group][blk][CAPT] tagged candidates: mantissa | (col_in_group << 23).
// Region = 96 B, 16B-aligned.
__device__ unsigned g_cand[(size_t)NGRP * NBLK * CAPT];
// [group][blk] packed meta: .x = 4x8b per-col candidate counts,
//                           .y = 4x8b per-col below counts.  2 MB.
__device__ uint2    g_meta[NGRP * NBLK];
__device__ __align__(16) float g_thr[C_DIM];

// -------------------------------------------------------------------------
// Pass 1 (R13-proven, 32us): one full read of x. Thread t exclusively owns
// columns 4t..4t+3 within its block; candidates append to ONE region.
// grid = 1024 blocks x 256 threads; each block covers 32 rows. MLP = 4.
// -------------------------------------------------------------------------
__global__ void __launch_bounds__(256) k_collect(const float4* __restrict__ x) {
    const int t    = threadIdx.x;            // == column group id
    const int blk  = blockIdx.x;
    const int row0 = blk * RPB;

    unsigned* cp = &g_cand[((size_t)t * NBLK + blk) * CAPT];

    int n_all = 0;        // total candidates appended to region
    unsigned cnts = 0;    // 4x8b per-col candidate counts
    unsigned bels = 0;    // 4x8b per-col below counts

#define PROC1(a, u)                                                           \
    do {                                                                      \
        bels += (unsigned)((a) < W_LO) << (8 * (u));                          \
        if ((a) >= W_LO && (a) <= W_HI) {                                     \
            if (n_all < CAPT)                                                 \
                cp[n_all] = (__float_as_uint(a) & MSK23) | ((unsigned)(u) << 23); \
            n_all++;                                                          \
            cnts += 1u << (8 * (u));                                          \
        }                                                                     \
    } while (0)

#define PROC(v)                                                               \
    do {                                                                      \
        PROC1(fabsf((v).x), 0);                                               \
        PROC1(fabsf((v).y), 1);                                               \
        PROC1(fabsf((v).z), 2);                                               \
        PROC1(fabsf((v).w), 3);                                               \
    } while (0)

    #pragma unroll
    for (int j0 = 0; j0 < RPB; j0 += 4) {
        // Front-batched independent loads: MLP = 4.
        float4 v0 = x[(size_t)(row0 + j0 + 0) * 256 + t];
        float4 v1 = x[(size_t)(row0 + j0 + 1) * 256 + t];
        float4 v2 = x[(size_t)(row0 + j0 + 2) * 256 + t];
        float4 v3 = x[(size_t)(row0 + j0 + 3) * 256 + t];
        PROC(v0);
        PROC(v1);
        PROC(v2);
        PROC(v3);
    }
#undef PROC
#undef PROC1

    g_meta[t * NBLK + blk] = make_uint2(cnts, bels);
}

// -------------------------------------------------------------------------
// Pass 2: one block per GROUP g (columns 4g..4g+3). No staging array:
// sweep 1 builds packed dual 2048-bin histograms straight from the region
// stream (bins = mantissa bits [22:12]; values share exponent 126 so
// mantissa order == value order); packed shfl scans + parallel rank-segment
// location; sweep 2 (cache-resident) gathers bin-mates; threads 0..3 resolve.
// Fallback (rank outside window / any region overflow): exact radix select.
// -------------------------------------------------------------------------
__global__ void __launch_bounds__(256) k_select(const float* __restrict__ x) {
    __shared__ int      histA[2048];      // col0 lo16 | col2 hi16
    __shared__ int      histB[2048];      // col1 lo16 | col3 hi16
    __shared__ unsigned ssmall[4][SMALLC];
    __shared__ int      s_smc[4];
    __shared__ int      s_bel[4], s_n[4], s_r[4], s_fb[4];
    __shared__ int      s_bin[4], s_r2[4];
    __shared__ int      s_any_over;
    __shared__ int      s_totA, s_totB;   // packed col totals (16b halves)
    __shared__ int      wsumA[8], wsumB[8];
    __shared__ unsigned s_prefix;
    __shared__ int      s_rank;

    const int g    = blockIdx.x;
    const int t    = threadIdx.x;
    const int lane = t & 31;
    const int wid  = t >> 5;

    if (t < 4) { s_bel[t] = 0; s_fb[t] = 0; s_smc[t] = 0; }
    if (t == 0) { s_any_over = 0; s_totA = 0; s_totB = 0; }
    #pragma unroll
    for (int q = 0; q < 8; ++q) { histA[t + q * 256] = 0; histB[t + q * 256] = 0; }
    __syncthreads();

    // ---- meta for my 4 regions (coalesced 32B/thread) ----
    int mtot[4];          // clamped region totals (safe read bound)
    int tc0 = 0, tc1 = 0, tc2 = 0, tc3 = 0;
    int bel0 = 0, bel1 = 0, bel2 = 0, bel3 = 0;
    bool over = false;
    #pragma unroll
    for (int rr = 0; rr < 4; ++rr) {
        const uint2 m = g_meta[g * NBLK + (t * 4 + rr)];
        const int b0 = (int)(m.x & 255u),         b1 = (int)((m.x >> 8) & 255u);
        const int b2 = (int)((m.x >> 16) & 255u), b3 = (int)(m.x >> 24);
        const int gt = b0 + b1 + b2 + b3;
        if (gt > CAPT) over = true;
        mtot[rr] = (gt > CAPT) ? CAPT : gt;
        tc0 += b0;  tc1 += b1;  tc2 += b2;  tc3 += b3;
        bel0 += (int)(m.y & 255u);         bel1 += (int)((m.y >> 8) & 255u);
        bel2 += (int)((m.y >> 16) & 255u); bel3 += (int)(m.y >> 24);
    }
    if (over) s_any_over = 1;
    atomicAdd(&s_bel[0], bel0);  atomicAdd(&s_bel[1], bel1);
    atomicAdd(&s_bel[2], bel2);  atomicAdd(&s_bel[3], bel3);
    // Packed totals: per-column sums <= ~1700 << 65536, halves never carry.
    atomicAdd(&s_totA, tc0 | (tc2 << 16));
    atomicAdd(&s_totB, tc1 | (tc3 << 16));

    // ---- sweep 1: histogram straight from the region stream ----
    #pragma unroll
    for (int rr = 0; rr < 4; ++rr) {
        const uint4* src = reinterpret_cast<const uint4*>(
            &g_cand[((size_t)g * NBLK + (t * 4 + rr)) * CAPT]);
        const uint4 q0 = src[0], q1 = src[1], q2 = src[2];
        const uint4 q3 = src[3], q4 = src[4], q5 = src[5];
        const unsigned wb[CAPT] = {
            q0.x, q0.y, q0.z, q0.w, q1.x, q1.y, q1.z, q1.w,
            q2.x, q2.y, q2.z, q2.w, q3.x, q3.y, q3.z, q3.w,
            q4.x, q4.y, q4.z, q4.w, q5.x, q5.y, q5.z, q5.w };
        const int m = mtot[rr];
        #pragma unroll
        for (int j = 0; j < CAPT; ++j) {
            if (j < m) {
                const unsigned w = wb[j];
                const unsigned u = w >> 23;
                int* h = (u & 1) ? histB : histA;
                atomicAdd(&h[(w & MSK23) >> 12], 1 << ((u & 2) << 3));
            }
        }
    }
    __syncthreads();

    if (t < 4) {
        const int n = (t == 0) ? (s_totA & 0xFFFF) :
                      (t == 1) ? (s_totB & 0xFFFF) :
                      (t == 2) ? (s_totA >> 16)    : (s_totB >> 16);
        const int r = RANK0 - s_bel[t];
        s_n[t] = n;
        s_r[t] = r;
        s_fb[t] = (s_any_over || r < 0 || r >= n) ? 1 : 0;
    }

    // ---- packed segment sums (8 bins each) + packed scans ----
    int sA = 0, sB = 0;
    #pragma unroll
    for (int q = 0; q < 8; ++q) { sA += histA[t * 8 + q]; sB += histB[t * 8 + q]; }
    int jA = sA, jB = sB;
    #pragma unroll
    for (int d = 1; d < 32; d <<= 1) {
        int oA = __shfl_up_sync(0xFFFFFFFFu, jA, d);
        int oB = __shfl_up_sync(0xFFFFFFFFu, jB, d);
        if (lane >= d) { jA += oA; jB += oB; }
    }
    if (lane == 31) { wsumA[wid] = jA; wsumB[wid] = jB; }
    __syncthreads();
    if (t == 0) {
        int aA = 0, aB = 0;
        #pragma unroll
        for (int i = 0; i < 8; ++i) {
            int ta = wsumA[i], tb = wsumB[i];
            wsumA[i] = aA; wsumB[i] = aB;
            aA += ta; aB += tb;
        }
    }
    __syncthreads();
    const int exA = wsumA[wid] + jA - sA;   // packed exclusive prefixes
    const int exB = wsumB[wid] + jB - sB;

    // ---- parallel rank-segment location: the one thread whose segment
    //      contains r walks its <=8 bins. Four columns concurrently. ----
#define FIND(uu, HH, ex, sg, SH)                                              \
    do {                                                                      \
        if (!s_fb[uu]) {                                                      \
            const int r_ = s_r[uu];                                           \
            const int e_ = ((ex) >> (SH)) & 0xFFFF;                           \
            const int g_ = ((sg) >> (SH)) & 0xFFFF;                           \
            if (e_ <= r_ && r_ < e_ + g_) {                                   \
                int cum = e_, b = t * 8;                                      \
                while (cum + (int)(((unsigned)HH[b] >> (SH)) & 0xFFFFu) <= r_) { \
                    cum += (int)(((unsigned)HH[b] >> (SH)) & 0xFFFFu);        \
                    ++b;                                                      \
                }                                                             \
                s_bin[uu] = b;                                                \
                s_r2[uu]  = r_ - cum;                                         \
            }                                                                 \
        }                                                                     \
    } while (0)
    FIND(0, histA, exA, sA, 0);
    FIND(1, histB, exB, sB, 0);
    FIND(2, histA, exA, sA, 16);
    FIND(3, histB, exB, sB, 16);
#undef FIND
    __syncthreads();

    // ---- sweep 2 (cache-resident): gather bin-mates ----
    {
        // Valid target bins; flagged columns get an impossible bin (2048).
        const int t0 = s_fb[0] ? 2048 : s_bin[0];
        const int t1 = s_fb[1] ? 2048 : s_bin[1];
        const int t2 = s_fb[2] ? 2048 : s_bin[2];
        const int t3 = s_fb[3] ? 2048 : s_bin[3];
        #pragma unroll
        for (int rr = 0; rr < 4; ++rr) {
            const uint4* src = reinterpret_cast<const uint4*>(
                &g_cand[((size_t)g * NBLK + (t * 4 + rr)) * CAPT]);
            const uint4 q0 = src[0], q1 = src[1], q2 = src[2];
            const uint4 q3 = src[3], q4 = src[4], q5 = src[5];
            const unsigned wb[CAPT] = {
                q0.x, q0.y, q0.z, q0.w, q1.x, q1.y, q1.z, q1.w,
                q2.x, q2.y, q2.z, q2.w, q3.x, q3.y, q3.z, q3.w,
                q4.x, q4.y, q4.z, q4.w, q5.x, q5.y, q5.z, q5.w };
            const int m = mtot[rr];
            #pragma unroll
            for (int j = 0; j < CAPT; ++j) {
                if (j < m) {
                    const unsigned w = wb[j];
                    const int u = (int)(w >> 23);
                    const int bin = (int)((w & MSK23) >> 12);
                    const int tgt = (u == 0) ? t0 : (u == 1) ? t1
                                  : (u == 2) ? t2 : t3;
                    if (bin == tgt) {
                        int p = atomicAdd(&s_smc[u], 1);
                        if (p < SMALLC) ssmall[u][p] = w & MSK23;
                    }
                }
            }
        }
    }
    __syncthreads();

    // ---- resolve: threads 0..3 handle one column each (m ~ 5) ----
    if (t < 4 && !s_fb[t]) {
        const int m = s_smc[t];
        if (m > SMALLC) {
            s_fb[t] = 1;                       // pathological: redo exactly
        } else {
            const int r2 = s_r2[t];
            unsigned ans = 0;
            for (int i = 0; i < m; ++i) {
                unsigned vv = ssmall[t][i];
                int less = 0, eq = 0;
                for (int j = 0; j < m; ++j) {
                    less += (ssmall[t][j] < vv);
                    eq   += (ssmall[t][j] == vv);
                }
                if (less <= r2 && r2 < less + eq) { ans = vv; break; }
            }
            g_thr[g * 4 + t] = __uint_as_float(ans | (126u << 23));
        }
    }
    __syncthreads();

    // ---- exact MSD radix-select fallback for any flagged column ----
    for (int u = 0; u < 4; ++u) {
        if (s_fb[u]) {
            const int c = g * 4 + u;
            if (t == 0) { s_prefix = 0; s_rank = RANK0; }
            for (int shift = 24; shift >= 0; shift -= 8) {
                histA[t] = 0;                  // only 256 bins used here
                __syncthreads();
                const unsigned pfx = s_prefix;
                const int hs = shift + 8;
                for (int row = t; row < N_ROWS; row += 256) {
                    unsigned key = __float_as_uint(fabsf(x[(size_t)row * C_DIM + c]));
                    bool ok = (hs >= 32) || ((key >> hs) == (pfx >> hs));
                    if (ok) atomicAdd(&histA[(key >> shift) & 255], 1);
                }
                __syncthreads();
                if (t == 0) {
                    int cum = 0, b = 0;
                    while (cum + histA[b] <= s_rank) { cum += histA[b]; ++b; }
                    s_rank  -= cum;
                    s_prefix |= ((unsigned)b) << shift;
                }
                __syncthreads();
            }
            if (t == 0) g_thr[c] = __uint_as_float(s_prefix);
            __syncthreads();
        }
    }
}

// -------------------------------------------------------------------------
// Pass 3 (R13-proven, ~40us streaming floor). blockDim must be 256 so each
// thread's column group (threadIdx.x) is loop-invariant -> threshold float4
// hoisted out of the loop.
// -------------------------------------------------------------------------
__global__ void __launch_bounds__(256) k_mask(const float4* __restrict__ x,
                                              float4* __restrict__ out,
                                              int n4) {
    const float4 thr = reinterpret_cast<const float4*>(g_thr)[threadIdx.x];
    const int stride = gridDim.x * blockDim.x;   // multiple of 256
    for (int i = blockIdx.x * blockDim.x + threadIdx.x; i < n4; i += stride) {
        float4 v = x[i];
        float4 o;
        o.x = (fabsf(v.x) <= thr.x) ? 0.0f : v.x;
        o.y = (fabsf(v.y) <= thr.y) ? 0.0f : v.y;
        o.z = (fabsf(v.z) <= thr.z) ? 0.0f : v.z;
        o.w = (fabsf(v.w) <= thr.w) ? 0.0f : v.w;
        out[i] = o;
    }
}

extern "C" void kernel_launch(void* const* d_in, const int* in_sizes, int n_in,
                              void* d_out, int out_size) {
    const float* x = (const float*)d_in[0];
    float* out     = (float*)d_out;
    const int n4   = out_size / 4;               // 8,388,608 float4s

    k_collect<<<NBLK, 256>>>((const float4*)x);
    k_select <<<NGRP, 256>>>(x);
    k_mask   <<<8192, 256>>>((const float4*)x, (float4*)out, n4);
}

// round 16
// speedup vs baseline: 1.1353x; 1.0425x over previous
#include <cuda_runtime.h>
#include <cuda_bf16.h>

// TargetedDropout inference path:
//   per channel c (last axis, C=1024), threshold = 16383-th smallest |x| over
//   the N=32768 leading entries; out = (|x| <= thr[c]) ? 0 : x.
//
// Round 15: select widened to 512 threads (2 regions/thread) to halve the
// per-thread serial chain; collect reads x with __ldcs so the 128MB stream
// stops evicting g_cand/meta from L2 before select reads them.
// Exact packed-histogram select; exact radix fallback per column.

#define C_DIM   1024
#define N_ROWS  32768
#define RANK0   16383            // int(0.5 * 32768) - 1
#define W_LO    0.64f
#define W_HI    0.71f
#define NBLK    1024             // collect blocks
#define RPB     (N_ROWS / NBLK)  // 32 rows per collect block
#define NGRP    256              // column groups (4 cols each)
#define CAPT    24               // per (group,blk) region cap (lambda = 5.69)
#define SMALLC  96               // bin-mate capacity (Poisson(~5) at 2048 bins)
#define MSK23   0x007FFFFFu
#define STH     512              // select threads per block

// [group][blk][CAPT] tagged candidates: mantissa | (col_in_group << 23).
// Region = 96 B, 16B-aligned.
__device__ unsigned g_cand[(size_t)NGRP * NBLK * CAPT];
// [group][blk] packed meta: .x = 4x8b per-col candidate counts,
//                           .y = 4x8b per-col below counts.  2 MB.
__device__ uint2    g_meta[NGRP * NBLK];
__device__ __align__(16) float g_thr[C_DIM];

// -------------------------------------------------------------------------
// Pass 1 (proven 32us): one full read of x (streaming hint). Thread t
// exclusively owns columns 4t..4t+3 within its block; candidates append to
// ONE region. grid = 1024 x 256; each block covers 32 rows. MLP = 4.
// -------------------------------------------------------------------------
__global__ void __launch_bounds__(256) k_collect(const float4* __restrict__ x) {
    const int t    = threadIdx.x;            // == column group id
    const int blk  = blockIdx.x;
    const int row0 = blk * RPB;

    unsigned* cp = &g_cand[((size_t)t * NBLK + blk) * CAPT];

    int n_all = 0;        // total candidates appended to region
    unsigned cnts = 0;    // 4x8b per-col candidate counts
    unsigned bels = 0;    // 4x8b per-col below counts

#define PROC1(a, u)                                                           \
    do {                                                                      \
        bels += (unsigned)((a) < W_LO) << (8 * (u));                          \
        if ((a) >= W_LO && (a) <= W_HI) {                                     \
            if (n_all < CAPT)                                                 \
                cp[n_all] = (__float_as_uint(a) & MSK23) | ((unsigned)(u) << 23); \
            n_all++;                                                          \
            cnts += 1u << (8 * (u));                                          \
        }                                                                     \
    } while (0)

#define PROC(v)                                                               \
    do {                                                                      \
        PROC1(fabsf((v).x), 0);                                               \
        PROC1(fabsf((v).y), 1);                                               \
        PROC1(fabsf((v).z), 2);                                               \
        PROC1(fabsf((v).w), 3);                                               \
    } while (0)

    #pragma unroll
    for (int j0 = 0; j0 < RPB; j0 += 4) {
        // Front-batched independent streaming loads: MLP = 4.
        float4 v0 = __ldcs(&x[(size_t)(row0 + j0 + 0) * 256 + t]);
        float4 v1 = __ldcs(&x[(size_t)(row0 + j0 + 1) * 256 + t]);
        float4 v2 = __ldcs(&x[(size_t)(row0 + j0 + 2) * 256 + t]);
        float4 v3 = __ldcs(&x[(size_t)(row0 + j0 + 3) * 256 + t]);
        PROC(v0);
        PROC(v1);
        PROC(v2);
        PROC(v3);
    }
#undef PROC
#undef PROC1

    g_meta[t * NBLK + blk] = make_uint2(cnts, bels);
}

// -------------------------------------------------------------------------
// Pass 2: one block per GROUP g (columns 4g..4g+3), 512 threads, 2 regions
// per thread. Sweep 1 builds packed dual 2048-bin histograms straight from
// the region stream (bins = mantissa bits [22:12]; values share exponent 126
// so mantissa order == value order); packed shfl scans + parallel
// rank-segment location; sweep 2 (L2-resident) gathers bin-mates; threads
// 0..3 resolve. Fallback (rank outside window / overflow): exact radix.
// -------------------------------------------------------------------------
__global__ void __launch_bounds__(STH) k_select(const float* __restrict__ x) {
    __shared__ int      histA[2048];      // col0 lo16 | col2 hi16
    __shared__ int      histB[2048];      // col1 lo16 | col3 hi16
    __shared__ unsigned ssmall[4][SMALLC];
    __shared__ int      s_smc[4];
    __shared__ int      s_bel[4], s_n[4], s_r[4], s_fb[4];
    __shared__ int      s_bin[4], s_r2[4];
    __shared__ int      s_any_over;
    __shared__ int      s_totA, s_totB;   // packed col totals (16b halves)
    __shared__ int      wsumA[16], wsumB[16];
    __shared__ unsigned s_prefix;
    __shared__ int      s_rank;

    const int g    = blockIdx.x;
    const int t    = threadIdx.x;
    const int lane = t & 31;
    const int wid  = t >> 5;              // 0..15

    if (t < 4) { s_bel[t] = 0; s_fb[t] = 0; s_smc[t] = 0; }
    if (t == 0) { s_any_over = 0; s_totA = 0; s_totB = 0; }
    #pragma unroll
    for (int q = 0; q < 4; ++q) { histA[t + q * STH] = 0; histB[t + q * STH] = 0; }
    __syncthreads();

    // ---- meta for my 2 regions (coalesced 16B/thread) ----
    int mtot[2];          // clamped region totals (safe read bound)
    int tc0 = 0, tc1 = 0, tc2 = 0, tc3 = 0;
    int bel0 = 0, bel1 = 0, bel2 = 0, bel3 = 0;
    bool over = false;
    #pragma unroll
    for (int rr = 0; rr < 2; ++rr) {
        const uint2 m = g_meta[g * NBLK + (t * 2 + rr)];
        const int b0 = (int)(m.x & 255u),         b1 = (int)((m.x >> 8) & 255u);
        const int b2 = (int)((m.x >> 16) & 255u), b3 = (int)(m.x >> 24);
        const int gt = b0 + b1 + b2 + b3;
        if (gt > CAPT) over = true;
        mtot[rr] = (gt > CAPT) ? CAPT : gt;
        tc0 += b0;  tc1 += b1;  tc2 += b2;  tc3 += b3;
        bel0 += (int)(m.y & 255u);         bel1 += (int)((m.y >> 8) & 255u);
        bel2 += (int)((m.y >> 16) & 255u); bel3 += (int)(m.y >> 24);
    }
    if (over) s_any_over = 1;
    if (bel0 | bel1 | bel2 | bel3) {
        atomicAdd(&s_bel[0], bel0);  atomicAdd(&s_bel[1], bel1);
        atomicAdd(&s_bel[2], bel2);  atomicAdd(&s_bel[3], bel3);
    }
    // Packed totals: per-column sums <= ~1700 << 65536, halves never carry.
    atomicAdd(&s_totA, tc0 | (tc2 << 16));
    atomicAdd(&s_totB, tc1 | (tc3 << 16));

    // ---- sweep 1: histogram straight from the region stream ----
    #pragma unroll
    for (int rr = 0; rr < 2; ++rr) {
        const uint4* src = reinterpret_cast<const uint4*>(
            &g_cand[((size_t)g * NBLK + (t * 2 + rr)) * CAPT]);
        const uint4 q0 = src[0], q1 = src[1], q2 = src[2];
        const uint4 q3 = src[3], q4 = src[4], q5 = src[5];
        const unsigned wb[CAPT] = {
            q0.x, q0.y, q0.z, q0.w, q1.x, q1.y, q1.z, q1.w,
            q2.x, q2.y, q2.z, q2.w, q3.x, q3.y, q3.z, q3.w,
            q4.x, q4.y, q4.z, q4.w, q5.x, q5.y, q5.z, q5.w };
        const int m = mtot[rr];
        #pragma unroll
        for (int j = 0; j < CAPT; ++j) {
            if (j < m) {
                const unsigned w = wb[j];
                const unsigned u = w >> 23;
                int* h = (u & 1) ? histB : histA;
                atomicAdd(&h[(w & MSK23) >> 12], 1 << ((u & 2) << 3));
            }
        }
    }
    __syncthreads();

    if (t < 4) {
        const int n = (t == 0) ? (s_totA & 0xFFFF) :
                      (t == 1) ? (s_totB & 0xFFFF) :
                      (t == 2) ? (s_totA >> 16)    : (s_totB >> 16);
        const int r = RANK0 - s_bel[t];
        s_n[t] = n;
        s_r[t] = r;
        s_fb[t] = (s_any_over || r < 0 || r >= n) ? 1 : 0;
    }

    // ---- packed segment sums (4 bins each) + packed scans (16 warps) ----
    int sA = 0, sB = 0;
    #pragma unroll
    for (int q = 0; q < 4; ++q) { sA += histA[t * 4 + q]; sB += histB[t * 4 + q]; }
    int jA = sA, jB = sB;
    #pragma unroll
    for (int d = 1; d < 32; d <<= 1) {
        int oA = __shfl_up_sync(0xFFFFFFFFu, jA, d);
        int oB = __shfl_up_sync(0xFFFFFFFFu, jB, d);
        if (lane >= d) { jA += oA; jB += oB; }
    }
    if (lane == 31) { wsumA[wid] = jA; wsumB[wid] = jB; }
    __syncthreads();
    if (t == 0) {
        int aA = 0, aB = 0;
        #pragma unroll
        for (int i = 0; i < 16; ++i) {
            int ta = wsumA[i], tb = wsumB[i];
            wsumA[i] = aA; wsumB[i] = aB;
            aA += ta; aB += tb;
        }
    }
    __syncthreads();
    const int exA = wsumA[wid] + jA - sA;   // packed exclusive prefixes
    const int exB = wsumB[wid] + jB - sB;

    // ---- parallel rank-segment location: the one thread whose segment
    //      contains r walks its <=4 bins. Four columns concurrently. ----
#define FIND(uu, HH, ex, sg, SH)                                              \
    do {                                                                      \
        if (!s_fb[uu]) {                                                      \
            const int r_ = s_r[uu];                                           \
            const int e_ = ((ex) >> (SH)) & 0xFFFF;                           \
            const int g_ = ((sg) >> (SH)) & 0xFFFF;                           \
            if (e_ <= r_ && r_ < e_ + g_) {                                   \
                int cum = e_, b = t * 4;                                      \
                while (cum + (int)(((unsigned)HH[b] >> (SH)) & 0xFFFFu) <= r_) { \
                    cum += (int)(((unsigned)HH[b] >> (SH)) & 0xFFFFu);        \
                    ++b;                                                      \
                }                                                             \
                s_bin[uu] = b;                                                \
                s_r2[uu]  = r_ - cum;                                         \
            }                                                                 \
        }                                                                     \
    } while (0)
    FIND(0, histA, exA, sA, 0);
    FIND(1, histB, exB, sB, 0);
    FIND(2, histA, exA, sA, 16);
    FIND(3, histB, exB, sB, 16);
#undef FIND
    __syncthreads();

    // ---- sweep 2 (L2-resident): gather bin-mates ----
    {
        // Valid target bins; flagged columns get an impossible bin (2048).
        const int t0 = s_fb[0] ? 2048 : s_bin[0];
        const int t1 = s_fb[1] ? 2048 : s_bin[1];
        const int t2 = s_fb[2] ? 2048 : s_bin[2];
        const int t3 = s_fb[3] ? 2048 : s_bin[3];
        #pragma unroll
        for (int rr = 0; rr < 2; ++rr) {
            const uint4* src = reinterpret_cast<const uint4*>(
                &g_cand[((size_t)g * NBLK + (t * 2 + rr)) * CAPT]);
            const uint4 q0 = src[0], q1 = src[1], q2 = src[2];
            const uint4 q3 = src[3], q4 = src[4], q5 = src[5];
            const unsigned wb[CAPT] = {
                q0.x, q0.y, q0.z, q0.w, q1.x, q1.y, q1.z, q1.w,
                q2.x, q2.y, q2.z, q2.w, q3.x, q3.y, q3.z, q3.w,
                q4.x, q4.y, q4.z, q4.w, q5.x, q5.y, q5.z, q5.w };
            const int m = mtot[rr];
            #pragma unroll
            for (int j = 0; j < CAPT; ++j) {
                if (j < m) {
                    const unsigned w = wb[j];
                    const int u = (int)(w >> 23);
                    const int bin = (int)((w & MSK23) >> 12);
                    const int tgt = (u == 0) ? t0 : (u == 1) ? t1
                                  : (u == 2) ? t2 : t3;
                    if (bin == tgt) {
                        int p = atomicAdd(&s_smc[u], 1);
                        if (p < SMALLC) ssmall[u][p] = w & MSK23;
                    }
                }
            }
        }
    }
    __syncthreads();

    // ---- resolve: threads 0..3 handle one column each (m ~ 5) ----
    if (t < 4 && !s_fb[t]) {
        const int m = s_smc[t];
        if (m > SMALLC) {
            s_fb[t] = 1;                       // pathological: redo exactly
        } else {
            const int r2 = s_r2[t];
            unsigned ans = 0;
            for (int i = 0; i < m; ++i) {
                unsigned vv = ssmall[t][i];
                int less = 0, eq = 0;
                for (int j = 0; j < m; ++j) {
                    less += (ssmall[t][j] < vv);
                    eq   += (ssmall[t][j] == vv);
                }
                if (less <= r2 && r2 < less + eq) { ans = vv; break; }
            }
            g_thr[g * 4 + t] = __uint_as_float(ans | (126u << 23));
        }
    }
    __syncthreads();

    // ---- exact MSD radix-select fallback for any flagged column ----
    for (int u = 0; u < 4; ++u) {
        if (s_fb[u]) {
            const int c = g * 4 + u;
            if (t == 0) { s_prefix = 0; s_rank = RANK0; }
            for (int shift = 24; shift >= 0; shift -= 8) {
                if (t < 256) histA[t] = 0;     // only 256 bins used here
                __syncthreads();
                const unsigned pfx = s_prefix;
                const int hs = shift + 8;
                for (int row = t; row < N_ROWS; row += STH) {
                    unsigned key = __float_as_uint(fabsf(x[(size_t)row * C_DIM + c]));
                    bool ok = (hs >= 32) || ((key >> hs) == (pfx >> hs));
                    if (ok) atomicAdd(&histA[(key >> shift) & 255], 1);
                }
                __syncthreads();
                if (t == 0) {
                    int cum = 0, b = 0;
                    while (cum + histA[b] <= s_rank) { cum += histA[b]; ++b; }
                    s_rank  -= cum;
                    s_prefix |= ((unsigned)b) << shift;
                }
                __syncthreads();
            }
            if (t == 0) g_thr[c] = __uint_as_float(s_prefix);
            __syncthreads();
        }
    }
}

// -------------------------------------------------------------------------
// Pass 3 (proven ~40us streaming floor). blockDim must be 256 so each
// thread's column group (threadIdx.x) is loop-invariant -> threshold float4
// hoisted out of the loop.
// -------------------------------------------------------------------------
__global__ void __launch_bounds__(256) k_mask(const float4* __restrict__ x,
                                              float4* __restrict__ out,
                                              int n4) {
    const float4 thr = reinterpret_cast<const float4*>(g_thr)[threadIdx.x];
    const int stride = gridDim.x * blockDim.x;   // multiple of 256
    for (int i = blockIdx.x * blockDim.x + threadIdx.x; i < n4; i += stride) {
        float4 v = x[i];
        float4 o;
        o.x = (fabsf(v.x) <= thr.x) ? 0.0f : v.x;
        o.y = (fabsf(v.y) <= thr.y) ? 0.0f : v.y;
        o.z = (fabsf(v.z) <= thr.z) ? 0.0f : v.z;
        o.w = (fabsf(v.w) <= thr.w) ? 0.0f : v.w;
        out[i] = o;
    }
}

extern "C" void kernel_launch(void* const* d_in, const int* in_sizes, int n_in,
                              void* d_out, int out_size) {
    const float* x = (const float*)d_in[0];
    float* out     = (float*)d_out;
    const int n4   = out_size / 4;               // 8,388,608 float4s

    k_collect<<<NBLK, 256>>>((const float4*)x);
    k_select <<<NGRP, STH>>>(x);
    k_mask   <<<8192, 256>>>((const float4*)x, (float4*)out, n4);
}

// round 17
// speedup vs baseline: 1.2944x; 1.1402x over previous
#include <cuda_runtime.h>
#include <cuda_bf16.h>

// TargetedDropout inference path:
//   per channel c (last axis, C=1024), threshold = 16383-th smallest |x| over
//   the N=32768 leading entries; out = (|x| <= thr[c]) ? 0 : x.
//
// Round 16: window narrowed to +-5-sigma around the N(0,1) sample median
// (fallback still exact); regions shrink to 16 words; select stages each
// thread's 2 regions in REGISTERS once and reuses them for both the
// histogram sweep and the bin-mate sweep (sweep 2 has zero global reads).
// Exact packed-histogram select; exact radix fallback per column.

#define C_DIM   1024
#define N_ROWS  32768
#define RANK0   16383            // int(0.5 * 32768) - 1
#define W_LO    0.6525f          // median 0.6745 +- 0.0044; +-5 sigma window
#define W_HI    0.6965f
#define NBLK    1024             // collect blocks
#define RPB     (N_ROWS / NBLK)  // 32 rows per collect block
#define NGRP    256              // column groups (4 cols each)
#define CAPT    16               // per (group,blk) region cap (lambda = 3.57)
#define SMALLC  96               // bin-mate capacity (Poisson(~5) per bin)
#define MSK23   0x007FFFFFu
#define STH     512              // select threads per block

// [group][blk][CAPT] tagged candidates: mantissa | (col_in_group << 23).
// Region = 64 B, 16B-aligned.
__device__ unsigned g_cand[(size_t)NGRP * NBLK * CAPT];
// [group][blk] packed meta: .x = 4x8b per-col candidate counts,
//                           .y = 4x8b per-col below counts.  2 MB.
__device__ uint2    g_meta[NGRP * NBLK];
__device__ __align__(16) float g_thr[C_DIM];

// -------------------------------------------------------------------------
// Pass 1 (proven ~32us shape): one full read of x (streaming hint). Thread t
// exclusively owns columns 4t..4t+3 within its block; candidates append to
// ONE region. grid = 1024 x 256; each block covers 32 rows. MLP = 4.
// -------------------------------------------------------------------------
__global__ void __launch_bounds__(256) k_collect(const float4* __restrict__ x) {
    const int t    = threadIdx.x;            // == column group id
    const int blk  = blockIdx.x;
    const int row0 = blk * RPB;

    unsigned* cp = &g_cand[((size_t)t * NBLK + blk) * CAPT];

    int n_all = 0;        // total candidates appended to region
    unsigned cnts = 0;    // 4x8b per-col candidate counts
    unsigned bels = 0;    // 4x8b per-col below counts

#define PROC1(a, u)                                                           \
    do {                                                                      \
        bels += (unsigned)((a) < W_LO) << (8 * (u));                          \
        if ((a) >= W_LO && (a) <= W_HI) {                                     \
            if (n_all < CAPT)                                                 \
                cp[n_all] = (__float_as_uint(a) & MSK23) | ((unsigned)(u) << 23); \
            n_all++;                                                          \
            cnts += 1u << (8 * (u));                                          \
        }                                                                     \
    } while (0)

#define PROC(v)                                                               \
    do {                                                                      \
        PROC1(fabsf((v).x), 0);                                               \
        PROC1(fabsf((v).y), 1);                                               \
        PROC1(fabsf((v).z), 2);                                               \
        PROC1(fabsf((v).w), 3);                                               \
    } while (0)

    #pragma unroll
    for (int j0 = 0; j0 < RPB; j0 += 4) {
        // Front-batched independent streaming loads: MLP = 4.
        float4 v0 = __ldcs(&x[(size_t)(row0 + j0 + 0) * 256 + t]);
        float4 v1 = __ldcs(&x[(size_t)(row0 + j0 + 1) * 256 + t]);
        float4 v2 = __ldcs(&x[(size_t)(row0 + j0 + 2) * 256 + t]);
        float4 v3 = __ldcs(&x[(size_t)(row0 + j0 + 3) * 256 + t]);
        PROC(v0);
        PROC(v1);
        PROC(v2);
        PROC(v3);
    }
#undef PROC
#undef PROC1

    g_meta[t * NBLK + blk] = make_uint2(cnts, bels);
}

// -------------------------------------------------------------------------
// Pass 2: one block per GROUP g (columns 4g..4g+3), 512 threads, 2 regions
// per thread, ALL 256 blocks resident in one wave. Each thread stages its
// regions in registers ONCE (8 independent uint4 loads, static indexing).
// Sweep 1: packed dual 2048-bin histograms (bins = mantissa bits [22:12];
// values share exponent 126 so mantissa order == value order). Packed shfl
// scans + parallel rank-segment location. Sweep 2 (register-only): gather
// bin-mates. Threads 0..3 resolve. Fallback: exact radix select.
// -------------------------------------------------------------------------
__global__ void __launch_bounds__(STH) k_select(const float* __restrict__ x) {
    __shared__ int      histA[2048];      // col0 lo16 | col2 hi16
    __shared__ int      histB[2048];      // col1 lo16 | col3 hi16
    __shared__ unsigned ssmall[4][SMALLC];
    __shared__ int      s_smc[4];
    __shared__ int      s_bel[4], s_n[4], s_r[4], s_fb[4];
    __shared__ int      s_bin[4], s_r2[4];
    __shared__ int      s_any_over;
    __shared__ int      s_totA, s_totB;   // packed col totals (16b halves)
    __shared__ int      wsumA[16], wsumB[16];
    __shared__ unsigned s_prefix;
    __shared__ int      s_rank;

    const int g    = blockIdx.x;
    const int t    = threadIdx.x;
    const int lane = t & 31;
    const int wid  = t >> 5;              // 0..15

    if (t < 4) { s_bel[t] = 0; s_fb[t] = 0; s_smc[t] = 0; }
    if (t == 0) { s_any_over = 0; s_totA = 0; s_totB = 0; }
    #pragma unroll
    for (int q = 0; q < 4; ++q) { histA[t + q * STH] = 0; histB[t + q * STH] = 0; }
    __syncthreads();

    // ---- stage: 2 meta words + 8 region uint4s, all independent (MLP=10) ----
    const uint2 m0 = g_meta[g * NBLK + (t * 2 + 0)];
    const uint2 m1 = g_meta[g * NBLK + (t * 2 + 1)];
    const uint4* s0 = reinterpret_cast<const uint4*>(
        &g_cand[((size_t)g * NBLK + (t * 2 + 0)) * CAPT]);
    const uint4* s1 = reinterpret_cast<const uint4*>(
        &g_cand[((size_t)g * NBLK + (t * 2 + 1)) * CAPT]);
    const uint4 a0 = s0[0], a1 = s0[1], a2 = s0[2], a3 = s0[3];
    const uint4 b0 = s1[0], b1 = s1[1], b2 = s1[2], b3 = s1[3];
    const unsigned wb[2 * CAPT] = {
        a0.x, a0.y, a0.z, a0.w, a1.x, a1.y, a1.z, a1.w,
        a2.x, a2.y, a2.z, a2.w, a3.x, a3.y, a3.z, a3.w,
        b0.x, b0.y, b0.z, b0.w, b1.x, b1.y, b1.z, b1.w,
        b2.x, b2.y, b2.z, b2.w, b3.x, b3.y, b3.z, b3.w };

    // ---- meta decode ----
    int tc0, tc1, tc2, tc3, mt0, mt1;
    bool over = false;
    {
        const int c00 = (int)(m0.x & 255u),         c01 = (int)((m0.x >> 8) & 255u);
        const int c02 = (int)((m0.x >> 16) & 255u), c03 = (int)(m0.x >> 24);
        const int c10 = (int)(m1.x & 255u),         c11 = (int)((m1.x >> 8) & 255u);
        const int c12 = (int)((m1.x >> 16) & 255u), c13 = (int)(m1.x >> 24);
        const int g0 = c00 + c01 + c02 + c03;
        const int g1 = c10 + c11 + c12 + c13;
        if (g0 > CAPT || g1 > CAPT) over = true;
        mt0 = (g0 > CAPT) ? CAPT : g0;
        mt1 = (g1 > CAPT) ? CAPT : g1;
        tc0 = c00 + c10;  tc1 = c01 + c11;  tc2 = c02 + c12;  tc3 = c03 + c13;
        const int bel0 = (int)(m0.y & 255u) + (int)(m1.y & 255u);
        const int bel1 = (int)((m0.y >> 8) & 255u) + (int)((m1.y >> 8) & 255u);
        const int bel2 = (int)((m0.y >> 16) & 255u) + (int)((m1.y >> 16) & 255u);
        const int bel3 = (int)(m0.y >> 24) + (int)(m1.y >> 24);
        if (over) s_any_over = 1;
        atomicAdd(&s_bel[0], bel0);  atomicAdd(&s_bel[1], bel1);
        atomicAdd(&s_bel[2], bel2);  atomicAdd(&s_bel[3], bel3);
        // Packed totals: per-column sums <= ~1100 << 65536, halves never carry.
        atomicAdd(&s_totA, tc0 | (tc2 << 16));
        atomicAdd(&s_totB, tc1 | (tc3 << 16));
    }

    // ---- sweep 1: histogram from the register-staged words ----
    #pragma unroll
    for (int j = 0; j < CAPT; ++j) {
        if (j < mt0) {
            const unsigned w = wb[j];
            const unsigned u = w >> 23;
            int* h = (u & 1) ? histB : histA;
            atomicAdd(&h[(w & MSK23) >> 12], 1 << ((u & 2) << 3));
        }
    }
    #pragma unroll
    for (int j = 0; j < CAPT; ++j) {
        if (j < mt1) {
            const unsigned w = wb[CAPT + j];
            const unsigned u = w >> 23;
            int* h = (u & 1) ? histB : histA;
            atomicAdd(&h[(w & MSK23) >> 12], 1 << ((u & 2) << 3));
        }
    }
    __syncthreads();

    if (t < 4) {
        const int n = (t == 0) ? (s_totA & 0xFFFF) :
                      (t == 1) ? (s_totB & 0xFFFF) :
                      (t == 2) ? (s_totA >> 16)    : (s_totB >> 16);
        const int r = RANK0 - s_bel[t];
        s_n[t] = n;
        s_r[t] = r;
        s_fb[t] = (s_any_over || r < 0 || r >= n) ? 1 : 0;
    }

    // ---- packed segment sums (4 bins each) + packed scans (16 warps) ----
    int sA = 0, sB = 0;
    #pragma unroll
    for (int q = 0; q < 4; ++q) { sA += histA[t * 4 + q]; sB += histB[t * 4 + q]; }
    int jA = sA, jB = sB;
    #pragma unroll
    for (int d = 1; d < 32; d <<= 1) {
        int oA = __shfl_up_sync(0xFFFFFFFFu, jA, d);
        int oB = __shfl_up_sync(0xFFFFFFFFu, jB, d);
        if (lane >= d) { jA += oA; jB += oB; }
    }
    if (lane == 31) { wsumA[wid] = jA; wsumB[wid] = jB; }
    __syncthreads();
    if (t == 0) {
        int aA = 0, aB = 0;
        #pragma unroll
        for (int i = 0; i < 16; ++i) {
            int ta = wsumA[i], tb = wsumB[i];
            wsumA[i] = aA; wsumB[i] = aB;
            aA += ta; aB += tb;
        }
    }
    __syncthreads();
    const int exA = wsumA[wid] + jA - sA;   // packed exclusive prefixes
    const int exB = wsumB[wid] + jB - sB;

    // ---- parallel rank-segment location: the one thread whose segment
    //      contains r walks its <=4 bins. Four columns concurrently. ----
#define FIND(uu, HH, ex, sg, SH)                                              \
    do {                                                                      \
        if (!s_fb[uu]) {                                                      \
            const int r_ = s_r[uu];                                           \
            const int e_ = ((ex) >> (SH)) & 0xFFFF;                           \
            const int g_ = ((sg) >> (SH)) & 0xFFFF;                           \
            if (e_ <= r_ && r_ < e_ + g_) {                                   \
                int cum = e_, b = t * 4;                                      \
                while (cum + (int)(((unsigned)HH[b] >> (SH)) & 0xFFFFu) <= r_) { \
                    cum += (int)(((unsigned)HH[b] >> (SH)) & 0xFFFFu);        \
                    ++b;                                                      \
                }                                                             \
                s_bin[uu] = b;                                                \
                s_r2[uu]  = r_ - cum;                                         \
            }                                                                 \
        }                                                                     \
    } while (0)
    FIND(0, histA, exA, sA, 0);
    FIND(1, histB, exB, sB, 0);
    FIND(2, histA, exA, sA, 16);
    FIND(3, histB, exB, sB, 16);
#undef FIND
    __syncthreads();

    // ---- sweep 2 (register-only): gather bin-mates ----
    {
        // Valid target bins; flagged columns get an impossible bin (2048).
        const int t0 = s_fb[0] ? 2048 : s_bin[0];
        const int t1 = s_fb[1] ? 2048 : s_bin[1];
        const int t2 = s_fb[2] ? 2048 : s_bin[2];
        const int t3 = s_fb[3] ? 2048 : s_bin[3];
        #pragma unroll
        for (int j = 0; j < CAPT; ++j) {
            if (j < mt0) {
                const unsigned w = wb[j];
                const int u = (int)(w >> 23);
                const int bin = (int)((w & MSK23) >> 12);
                const int tgt = (u == 0) ? t0 : (u == 1) ? t1
                              : (u == 2) ? t2 : t3;
                if (bin == tgt) {
                    int p = atomicAdd(&s_smc[u], 1);
                    if (p < SMALLC) ssmall[u][p] = w & MSK23;
                }
            }
        }
        #pragma unroll
        for (int j = 0; j < CAPT; ++j) {
            if (j < mt1) {
                const unsigned w = wb[CAPT + j];
                const int u = (int)(w >> 23);
                const int bin = (int)((w & MSK23) >> 12);
                const int tgt = (u == 0) ? t0 : (u == 1) ? t1
                              : (u == 2) ? t2 : t3;
                if (bin == tgt) {
                    int p = atomicAdd(&s_smc[u], 1);
                    if (p < SMALLC) ssmall[u][p] = w & MSK23;
                }
            }
        }
    }
    __syncthreads();

    // ---- resolve: threads 0..3 handle one column each (m ~ 5) ----
    if (t < 4 && !s_fb[t]) {
        const int m = s_smc[t];
        if (m > SMALLC) {
            s_fb[t] = 1;                       // pathological: redo exactly
        } else {
            const int r2 = s_r2[t];
            unsigned ans = 0;
            for (int i = 0; i < m; ++i) {
                unsigned vv = ssmall[t][i];
                int less = 0, eq = 0;
                for (int j = 0; j < m; ++j) {
                    less += (ssmall[t][j] < vv);
                    eq   += (ssmall[t][j] == vv);
                }
                if (less <= r2 && r2 < less + eq) { ans = vv; break; }
            }
            g_thr[g * 4 + t] = __uint_as_float(ans | (126u << 23));
        }
    }
    __syncthreads();

    // ---- exact MSD radix-select fallback for any flagged column ----
    for (int u = 0; u < 4; ++u) {
        if (s_fb[u]) {
            const int c = g * 4 + u;
            if (t == 0) { s_prefix = 0; s_rank = RANK0; }
            for (int shift = 24; shift >= 0; shift -= 8) {
                if (t < 256) histA[t] = 0;     // only 256 bins used here
                __syncthreads();
                const unsigned pfx = s_prefix;
                const int hs = shift + 8;
                for (int row = t; row < N_ROWS; row += STH) {
                    unsigned key = __float_as_uint(fabsf(x[(size_t)row * C_DIM + c]));
                    bool ok = (hs >= 32) || ((key >> hs) == (pfx >> hs));
                    if (ok) atomicAdd(&histA[(key >> shift) & 255], 1);
                }
                __syncthreads();
                if (t == 0) {
                    int cum = 0, b = 0;
                    while (cum + histA[b] <= s_rank) { cum += histA[b]; ++b; }
                    s_rank  -= cum;
                    s_prefix |= ((unsigned)b) << shift;
                }
                __syncthreads();
            }
            if (t == 0) g_thr[c] = __uint_as_float(s_prefix);
            __syncthreads();
        }
    }
}

// -------------------------------------------------------------------------
// Pass 3 (proven ~40us streaming floor). blockDim must be 256 so each
// thread's column group (threadIdx.x) is loop-invariant -> threshold float4
// hoisted out of the loop.
// -------------------------------------------------------------------------
__global__ void __launch_bounds__(256) k_mask(const float4* __restrict__ x,
                                              float4* __restrict__ out,
                                              int n4) {
    const float4 thr = reinterpret_cast<const float4*>(g_thr)[threadIdx.x];
    const int stride = gridDim.x * blockDim.x;   // multiple of 256
    for (int i = blockIdx.x * blockDim.x + threadIdx.x; i < n4; i += stride) {
        float4 v = x[i];
        float4 o;
        o.x = (fabsf(v.x) <= thr.x) ? 0.0f : v.x;
        o.y = (fabsf(v.y) <= thr.y) ? 0.0f : v.y;
        o.z = (fabsf(v.z) <= thr.z) ? 0.0f : v.z;
        o.w = (fabsf(v.w) <= thr.w) ? 0.0f : v.w;
        out[i] = o;
    }
}

extern "C" void kernel_launch(void* const* d_in, const int* in_sizes, int n_in,
                              void* d_out, int out_size) {
    const float* x = (const float*)d_in[0];
    float* out     = (float*)d_out;
    const int n4   = out_size / 4;               // 8,388,608 float4s

    k_collect<<<NBLK, 256>>>((const float4*)x);
    k_select <<<NGRP, STH>>>(x);
    k_mask   <<<8192, 256>>>((const float4*)x, (float4*)out, n4);
}